// round 11
// baseline (speedup 1.0000x reference)
#include <cuda_runtime.h>
#include <cstdint>

#define N_SRC 65536
#define N_DST 8192
#define MAXN  32
#define H     128

typedef unsigned long long ULL;

// ---------------- f32x2 helpers ----------------
__device__ __forceinline__ void ffma2(ULL& d, ULL a, ULL b) {
    asm("fma.rn.f32x2 %0, %1, %2, %3;" : "=l"(d) : "l"(a), "l"(b), "l"(d));
}
__device__ __forceinline__ ULL pk2(float x, float y) {
    ULL r; asm("mov.b64 %0, {%1, %2};" : "=l"(r) : "f"(x), "f"(y)); return r;
}
__device__ __forceinline__ float2 upk2(ULL v) {
    float2 f; asm("mov.b64 {%0, %1}, %2;" : "=f"(f.x), "=f"(f.y) : "l"(v)); return f;
}

// ---------------- tf32 mma helpers ----------------
__device__ __forceinline__ uint32_t tf32r(float x) {
    uint32_t r; asm("cvt.rna.tf32.f32 %0, %1;" : "=r"(r) : "f"(x)); return r;
}
__device__ __forceinline__ void mma_tf32(float& d0, float& d1, float& d2, float& d3,
    uint32_t a0, uint32_t a1, uint32_t a2, uint32_t a3, uint32_t b0, uint32_t b1)
{
    asm volatile("mma.sync.aligned.m16n8k8.row.col.f32.tf32.tf32.f32 "
        "{%0,%1,%2,%3}, {%4,%5,%6,%7}, {%8,%9}, {%0,%1,%2,%3};"
        : "+f"(d0), "+f"(d1), "+f"(d2), "+f"(d3)
        : "r"(a0), "r"(a1), "r"(a2), "r"(a3), "r"(b0), "r"(b1));
}

// ---------------- scratch ----------------
__device__ __align__(16) float g_feat_sim[N_SRC * H];
__device__ __align__(16) float g_feat_cor[N_SRC * H];
__device__ __align__(16) float g_rst_sim[N_DST * H];
__device__ __align__(16) float g_rst_cor[N_DST * H];
__device__ __align__(16) float g_H1[H * H];
__device__ __align__(16) float g_H2[H * H];
__device__ __align__(16) float g_M[256 * 256];
__device__ __align__(16) float g_c[256];

// ---------------- feat via tf32 MMA, A-side compensated ----------------
// CTA: 256 threads (8 warps), 32 rows x 128 cols. A stored as (hi,lo) tf32
// pairs (float2, pad 132 -> conflict-benign LDS.64); W single tf32, natural
// [k][n] layout, pad 136 (stride 544B = 32 mod 128 -> conflict-free B frags).
// Warp w: m-tile mt=w&1 (16 rows), n-range nt=w>>1 (32 cols = 4 n8 subtiles).
// Per k8 chunk: 4 LDS.64 A-frags, per subtile 2 LDS.32 B + 2 MMA (hi, lo).
struct FeatSmem {
    float2 A2[32][132];    // 33792 B
    float  Wt[128][136];   // 69632 B
    int2   xs[32];
};
#define FEAT_SMEM ((int)sizeof(FeatSmem))

__global__ __launch_bounds__(256) void feat_mma_kernel(
    const int* __restrict__ x,
    const float* __restrict__ e0s, const float* __restrict__ e1s,
    const float* __restrict__ Ws,  const float* __restrict__ bs, float* __restrict__ outs,
    const float* __restrict__ e0c, const float* __restrict__ e1c,
    const float* __restrict__ Wc,  const float* __restrict__ bc, float* __restrict__ outc)
{
    extern __shared__ char smem_raw[];
    FeatSmem& S = *reinterpret_cast<FeatSmem*>(smem_raw);

    const int halfgrid = N_SRC / 32;
    const bool is_sim = blockIdx.x < halfgrid;
    const int  blk    = is_sim ? blockIdx.x : blockIdx.x - halfgrid;
    const float* emb0 = is_sim ? e0s : e0c;
    const float* emb1 = is_sim ? e1s : e1c;
    const float* W    = is_sim ? Ws  : Wc;
    const float* b    = is_sim ? bs  : bc;
    float*       out  = is_sim ? outs : outc;

    const int base = blk * 32;
    const int tid = threadIdx.x;

    if (tid < 32) S.xs[tid] = ((const int2*)x)[base + tid];

    // ---- fill W (tf32-rounded), natural layout, coalesced ----
    for (int idx = tid; idx < 128 * 32; idx += 256) {
        const int k = idx >> 5;
        const int n4 = (idx & 31) * 4;
        const float4 wv = ((const float4*)W)[idx];
        S.Wt[k][n4 + 0] = __uint_as_float(tf32r(wv.x));
        S.Wt[k][n4 + 1] = __uint_as_float(tf32r(wv.y));
        S.Wt[k][n4 + 2] = __uint_as_float(tf32r(wv.z));
        S.Wt[k][n4 + 3] = __uint_as_float(tf32r(wv.w));
    }
    __syncthreads();

    // ---- gather A (32 rows) with exact hi/lo tf32 split ----
    {
        const int k = tid & 127;
        const int rbase = (tid >> 7) * 16;
#pragma unroll
        for (int i = 0; i < 16; i++) {
            const int r = rbase + i;
            const float v = (k < 32) ? emb0[S.xs[r].x * 32 + k]
                                     : emb1[S.xs[r].y * 96 + (k - 32)];
            const uint32_t hb = tf32r(v);
            const float hf = __uint_as_float(hb);
            const uint32_t lb = tf32r(v - hf);     // exact residual, then rounded
            S.A2[r][k] = make_float2(hf, __uint_as_float(lb));
        }
    }
    __syncthreads();

    // ---- mainloop ----
    const int lane = tid & 31, w = tid >> 5;
    const int mt = w & 1, nt = w >> 1;
    const int gid = lane >> 2, tig = lane & 3;
    const int rA0 = mt * 16 + gid;
    const int rA1 = rA0 + 8;

    float acc[4][4];
#pragma unroll
    for (int s = 0; s < 4; s++)
#pragma unroll
        for (int i = 0; i < 4; i++) acc[s][i] = 0.f;

#pragma unroll
    for (int kc = 0; kc < 16; kc++) {
        const int k0 = kc * 8;
        const float2 fa0 = S.A2[rA0][k0 + tig];
        const float2 fa1 = S.A2[rA1][k0 + tig];
        const float2 fa2 = S.A2[rA0][k0 + tig + 4];
        const float2 fa3 = S.A2[rA1][k0 + tig + 4];
        const uint32_t a0h = __float_as_uint(fa0.x), a0l = __float_as_uint(fa0.y);
        const uint32_t a1h = __float_as_uint(fa1.x), a1l = __float_as_uint(fa1.y);
        const uint32_t a2h = __float_as_uint(fa2.x), a2l = __float_as_uint(fa2.y);
        const uint32_t a3h = __float_as_uint(fa3.x), a3l = __float_as_uint(fa3.y);
#pragma unroll
        for (int sub = 0; sub < 4; sub++) {
            const int n = nt * 32 + sub * 8 + gid;
            const uint32_t b0 = __float_as_uint(S.Wt[k0 + tig][n]);
            const uint32_t b1 = __float_as_uint(S.Wt[k0 + tig + 4][n]);
            mma_tf32(acc[sub][0], acc[sub][1], acc[sub][2], acc[sub][3],
                     a0h, a1h, a2h, a3h, b0, b1);
            mma_tf32(acc[sub][0], acc[sub][1], acc[sub][2], acc[sub][3],
                     a0l, a1l, a2l, a3l, b0, b1);
        }
    }

    // ---- epilogue: + bias, direct STG.64 ----
#pragma unroll
    for (int sub = 0; sub < 4; sub++) {
        const int n = nt * 32 + sub * 8 + 2 * tig;
        const float2 bv = *(const float2*)&b[n];
        float2 r0 = make_float2(acc[sub][0] + bv.x, acc[sub][1] + bv.y);
        float2 r1 = make_float2(acc[sub][2] + bv.x, acc[sub][3] + bv.y);
        *(float2*)&out[(base + rA0) * H + n] = r0;
        *(float2*)&out[(base + rA1) * H + n] = r1;
    }
}

// ---------------- co-attention pool (R6 version, reverted) ----------------
__global__ __launch_bounds__(256) void attn_kernel(
    const float* __restrict__ feat_sim, const float* __restrict__ feat_cor,
    const int* __restrict__ neigh_sim, const int* __restrict__ neigh_cor,
    float* __restrict__ rst_sim, float* __restrict__ rst_cor)
{
    __shared__ float Ds[32][132];
    __shared__ float Qs[32][132];
    __shared__ float Es[32][33];
    __shared__ float invcol[32];
    __shared__ float invrow[32];
    __shared__ float wv[32];
    __shared__ float vv[32];
    __shared__ float coef[32];
    __shared__ float O[3 * H];

    const bool is_sim = blockIdx.x < N_DST;
    const int  node   = is_sim ? blockIdx.x : (blockIdx.x - N_DST);
    const float* feat = is_sim ? feat_sim : feat_cor;
    const int* idxD = is_sim ? neigh_cor : neigh_sim;   // sim: D = nf_cor
    const int* idxQ = is_sim ? neigh_sim : neigh_cor;
    float*     rst  = is_sim ? rst_sim : rst_cor;

    const int tid = threadIdx.x;
    const int lane = tid & 31;
    const int w = tid >> 5;

#pragma unroll
    for (int i = 0; i < 4; i++) {
        const int r = w * 4 + i;
        const int id = idxD[node * 32 + r];
        ((float4*)&Ds[r][0])[lane] = ((const float4*)feat)[id * 32 + lane];
        const int iq = idxQ[node * 32 + r];
        ((float4*)&Qs[r][0])[lane] = ((const float4*)feat)[iq * 32 + lane];
    }
    __syncthreads();

    {
        const int mt = w & 1;
        const int nt = w >> 1;
        const int gid = lane >> 2;
        const int tig = lane & 3;
        const int rA0 = mt * 16 + gid;
        const int rA1 = rA0 + 8;
        const int cn  = nt * 8 + gid;

        float c0 = 0.f, c1 = 0.f, c2 = 0.f, c3 = 0.f;
#pragma unroll
        for (int kc = 0; kc < 16; kc++) {
            const int k0 = kc * 8;
            const uint32_t a0 = tf32r(Ds[rA0][k0 + tig]);
            const uint32_t a1 = tf32r(Ds[rA1][k0 + tig]);
            const uint32_t a2 = tf32r(Ds[rA0][k0 + tig + 4]);
            const uint32_t a3 = tf32r(Ds[rA1][k0 + tig + 4]);
            const uint32_t b0 = tf32r(Qs[cn][k0 + tig]);
            const uint32_t b1 = tf32r(Qs[cn][k0 + tig + 4]);
            mma_tf32(c0, c1, c2, c3, a0, a1, a2, a3, b0, b1);
        }
        const int ec = nt * 8 + 2 * tig;
        Es[rA0][ec]     = __expf(c0);
        Es[rA0][ec + 1] = __expf(c1);
        Es[rA1][ec]     = __expf(c2);
        Es[rA1][ec + 1] = __expf(c3);
    }
    __syncthreads();

    if (w == 0) {
        const int m = lane;
        float s = 0.f;
#pragma unroll
        for (int k = 0; k < 32; k++) s += Es[m][k];
        invrow[m] = __frcp_rn(s);
    } else if (w == 1) {
        const int k = lane;
        float s = 0.f;
#pragma unroll
        for (int m = 0; m < 32; m++) s += Es[m][k];
        invcol[k] = __frcp_rn(s);
    }
    __syncthreads();

    if (w == 0) {
        const int m = lane;
        float s = 0.f;
#pragma unroll
        for (int k = 0; k < 32; k++) s += Es[m][k] * invcol[k];
        wv[m] = s;
        coef[m] = s * invrow[m];
    }
    __syncthreads();

    if (w == 1) {
        const int k = lane;
        float s = 0.f;
#pragma unroll
        for (int m = 0; m < 32; m++) s += coef[m] * Es[m][k];
        vv[k] = s;
    }
    __syncthreads();

    if (tid < 128) {
        const int h = tid;
        float sq = 0.f, scq = 0.f;
#pragma unroll
        for (int m = 0; m < 32; m++) {
            const float q = Qs[m][h];
            sq  += q;
            scq += vv[m] * q;
        }
        O[h]         = sq;
        O[2 * H + h] = scq;
    } else {
        const int h = tid - 128;
        float sdw = 0.f;
#pragma unroll
        for (int m = 0; m < 32; m++) sdw += wv[m] * Ds[m][h];
        O[H + h] = sdw;
    }
    __syncthreads();

    if (tid < 128) {
        const int h = tid;
        const float r = (O[3 * h] + O[3 * h + 1] + O[3 * h + 2]) * (1.f / 96.f);
        rst[node * H + h] = feat[node * H + h] + r;
    }
}

// ---------------- precompute: H1 = Wos@Ws2c, H2 = Woc@Wc2s ----------------
__global__ __launch_bounds__(128) void pre1_kernel(
    const float* __restrict__ Wos, const float* __restrict__ Ws2c,
    const float* __restrict__ Woc, const float* __restrict__ Wc2s,
    float* __restrict__ H1, float* __restrict__ H2)
{
    const bool first = blockIdx.x < H;
    const int r = first ? blockIdx.x : blockIdx.x - H;
    const float* U = first ? Wos : Woc;
    const float* V = first ? Ws2c : Wc2s;
    float* Oo = first ? H1 : H2;
    const int j = threadIdx.x;
    float s = 0.f;
#pragma unroll 4
    for (int k = 0; k < H; k++) s += U[r * H + k] * V[k * H + j];
    Oo[r * H + j] = s;
}

// ---------------- precompute: M quadrants ----------------
__global__ __launch_bounds__(128) void pre2_kernel(
    const float* __restrict__ Wos, const float* __restrict__ Woc,
    const float* __restrict__ Ws2c, const float* __restrict__ Wc2s,
    const float* __restrict__ H1, const float* __restrict__ H2,
    float* __restrict__ M)
{
    const int quad = blockIdx.x >> 7;
    const int r = blockIdx.x & 127;
    const int j = threadIdx.x;
    if (quad == 0) {
        float s = 0.f;
#pragma unroll 4
        for (int k = 0; k < H; k++) s += H1[r * H + k] * Wc2s[k * H + j];
        M[r * 256 + j] = 0.34f * Wos[r * H + j] + 0.165f * s;
    } else if (quad == 1) {
        M[r * 256 + 128 + j] = 0.495f * H1[r * H + j];
    } else if (quad == 2) {
        M[(128 + r) * 256 + j] = 0.495f * H2[r * H + j];
    } else {
        float s = 0.f;
#pragma unroll 4
        for (int k = 0; k < H; k++) s += H2[r * H + k] * Ws2c[k * H + j];
        M[(128 + r) * 256 + 128 + j] = 0.34f * Woc[r * H + j] + 0.165f * s;
    }
}

// ---------------- precompute: fused bias c ----------------
__global__ __launch_bounds__(128) void pre3_kernel(
    const float* __restrict__ bos, const float* __restrict__ boc,
    const float* __restrict__ Ws2c, const float* __restrict__ Wc2s,
    float* __restrict__ c)
{
    __shared__ float u[H], v[H];
    const int j = threadIdx.x;
    float su = 0.f, sv = 0.f;
    for (int k = 0; k < H; k++) {
        su += bos[k] * Ws2c[k * H + j];
        sv += boc[k] * Wc2s[k * H + j];
    }
    u[j] = su; v[j] = sv;
    __syncthreads();
    float t1 = 0.f, t2 = 0.f;
    for (int k = 0; k < H; k++) {
        t1 += u[k] * Wc2s[k * H + j];
        t2 += v[k] * Ws2c[k * H + j];
    }
    c[j]       = 0.34f * bos[j] + 0.165f * t1 + 0.495f * v[j];
    c[128 + j] = 0.34f * boc[j] + 0.165f * t2 + 0.495f * u[j];
}

// ---------------- fused final GEMM ----------------
__global__ __launch_bounds__(128) void mix_kernel(
    const float* __restrict__ rst_sim, const float* __restrict__ rst_cor,
    const float* __restrict__ M, const float* __restrict__ c,
    float* __restrict__ out)
{
    __shared__ float xb[256][34];
    const int base = blockIdx.x * 32;
    const int tid = threadIdx.x;

    for (int kk = tid; kk < 256; kk += 128) {
        const float* src = (kk < 128) ? (rst_sim + (size_t)base * H + kk)
                                      : (rst_cor + (size_t)base * H + (kk - 128));
#pragma unroll 4
        for (int r = 0; r < 32; r++) xb[kk][r] = src[r * H];
    }
    __syncthreads();

    const int j0 = tid;
    const int j1 = tid + 128;
    ULL acc0[16], acc1[16];
#pragma unroll
    for (int rp = 0; rp < 16; rp++) { acc0[rp] = 0ULL; acc1[rp] = 0ULL; }

#pragma unroll 2
    for (int k = 0; k < 256; k++) {
        const float w0 = M[k * 256 + j0];
        const float w1 = M[k * 256 + j1];
        const ULL wd0 = pk2(w0, w0);
        const ULL wd1 = pk2(w1, w1);
        const ULL* xp = (const ULL*)&xb[k][0];
#pragma unroll
        for (int rp = 0; rp < 16; rp++) {
            const ULL xv = xp[rp];
            ffma2(acc0[rp], xv, wd0);
            ffma2(acc1[rp], xv, wd1);
        }
    }

    const float c0 = c[j0], c1 = c[j1];
    float* o0 = out + j0;
    float* o1 = out + (size_t)N_DST * H + tid;
#pragma unroll
    for (int rp = 0; rp < 16; rp++) {
        const float2 f0 = upk2(acc0[rp]);
        const float2 f1 = upk2(acc1[rp]);
        o0[(size_t)(base + 2 * rp + 0) * H] = f0.x + c0;
        o0[(size_t)(base + 2 * rp + 1) * H] = f0.y + c0;
        o1[(size_t)(base + 2 * rp + 0) * H] = f1.x + c1;
        o1[(size_t)(base + 2 * rp + 1) * H] = f1.y + c1;
    }
}

// ---------------- launch ----------------
extern "C" void kernel_launch(void* const* d_in, const int* in_sizes, int n_in,
                              void* d_out, int out_size)
{
    const int*   x         = (const int*)d_in[0];
    const int*   neigh_sim = (const int*)d_in[1];
    const int*   neigh_cor = (const int*)d_in[2];
    const float* emb0_sim  = (const float*)d_in[3];
    const float* emb1_sim  = (const float*)d_in[4];
    const float* emb0_cor  = (const float*)d_in[5];
    const float* emb1_cor  = (const float*)d_in[6];
    const float* W_in_sim  = (const float*)d_in[7];
    const float* b_in_sim  = (const float*)d_in[8];
    const float* W_in_cor  = (const float*)d_in[9];
    const float* b_in_cor  = (const float*)d_in[10];
    const float* W_out_sim = (const float*)d_in[11];
    const float* b_out_sim = (const float*)d_in[12];
    const float* W_out_cor = (const float*)d_in[13];
    const float* b_out_cor = (const float*)d_in[14];
    const float* W_sim2cor = (const float*)d_in[15];
    const float* W_cor2sim = (const float*)d_in[16];

    float *feat_sim, *feat_cor, *rst_sim, *rst_cor, *H1, *H2, *M, *c;
    cudaGetSymbolAddress((void**)&feat_sim, g_feat_sim);
    cudaGetSymbolAddress((void**)&feat_cor, g_feat_cor);
    cudaGetSymbolAddress((void**)&rst_sim,  g_rst_sim);
    cudaGetSymbolAddress((void**)&rst_cor,  g_rst_cor);
    cudaGetSymbolAddress((void**)&H1,       g_H1);
    cudaGetSymbolAddress((void**)&H2,       g_H2);
    cudaGetSymbolAddress((void**)&M,        g_M);
    cudaGetSymbolAddress((void**)&c,        g_c);

    float* out = (float*)d_out;

    cudaFuncSetAttribute(feat_mma_kernel, cudaFuncAttributeMaxDynamicSharedMemorySize, FEAT_SMEM);

    pre1_kernel<<<2 * H, 128>>>(W_out_sim, W_sim2cor, W_out_cor, W_cor2sim, H1, H2);
    pre2_kernel<<<4 * H, 128>>>(W_out_sim, W_out_cor, W_sim2cor, W_cor2sim, H1, H2, M);
    pre3_kernel<<<1, 128>>>(b_out_sim, b_out_cor, W_sim2cor, W_cor2sim, c);

    feat_mma_kernel<<<2 * (N_SRC / 32), 256, FEAT_SMEM>>>(x,
        emb0_sim, emb1_sim, W_in_sim, b_in_sim, feat_sim,
        emb0_cor, emb1_cor, W_in_cor, b_in_cor, feat_cor);

    attn_kernel<<<2 * N_DST, 256>>>(feat_sim, feat_cor, neigh_sim, neigh_cor,
                                    rst_sim, rst_cor);

    mix_kernel<<<N_DST / 32, 128>>>(rst_sim, rst_cor, M, c, out);
}

// round 12
// speedup vs baseline: 1.1272x; 1.1272x over previous
#include <cuda_runtime.h>
#include <cstdint>

#define N_SRC 65536
#define N_DST 8192
#define MAXN  32
#define H     128

typedef unsigned long long ULL;

// ---------------- f32x2 helpers ----------------
__device__ __forceinline__ void ffma2(ULL& d, ULL a, ULL b) {
    asm("fma.rn.f32x2 %0, %1, %2, %3;" : "=l"(d) : "l"(a), "l"(b), "l"(d));
}
__device__ __forceinline__ ULL pk2(float x, float y) {
    ULL r; asm("mov.b64 %0, {%1, %2};" : "=l"(r) : "f"(x), "f"(y)); return r;
}
__device__ __forceinline__ float2 upk2(ULL v) {
    float2 f; asm("mov.b64 {%0, %1}, %2;" : "=f"(f.x), "=f"(f.y) : "l"(v)); return f;
}

// ---------------- tf32 mma helpers ----------------
__device__ __forceinline__ uint32_t tf32r(float x) {
    uint32_t r; asm("cvt.rna.tf32.f32 %0, %1;" : "=r"(r) : "f"(x)); return r;
}
__device__ __forceinline__ void mma_tf32(float& d0, float& d1, float& d2, float& d3,
    uint32_t a0, uint32_t a1, uint32_t a2, uint32_t a3, uint32_t b0, uint32_t b1)
{
    asm volatile("mma.sync.aligned.m16n8k8.row.col.f32.tf32.tf32.f32 "
        "{%0,%1,%2,%3}, {%4,%5,%6,%7}, {%8,%9}, {%0,%1,%2,%3};"
        : "+f"(d0), "+f"(d1), "+f"(d2), "+f"(d3)
        : "r"(a0), "r"(a1), "r"(a2), "r"(a3), "r"(b0), "r"(b1));
}

// ---------------- scratch ----------------
__device__ __align__(16) float g_feat_sim[N_SRC * H];
__device__ __align__(16) float g_feat_cor[N_SRC * H];
__device__ __align__(16) float g_rst_sim[N_DST * H];
__device__ __align__(16) float g_rst_cor[N_DST * H];
__device__ __align__(16) float g_Wts[H * H];    // tf32-rounded W_in_sim
__device__ __align__(16) float g_Wtc[H * H];    // tf32-rounded W_in_cor
__device__ __align__(16) float g_H1[H * H];
__device__ __align__(16) float g_H2[H * H];
__device__ __align__(16) float g_M[256 * 256];
__device__ __align__(16) float g_c[256];

// ---------------- preW: tf32-round W_in into globals ----------------
__global__ __launch_bounds__(256) void preW_kernel(
    const float* __restrict__ Ws, const float* __restrict__ Wc,
    float* __restrict__ Wts, float* __restrict__ Wtc)
{
    const int i = blockIdx.x * 256 + threadIdx.x;
    Wts[i] = __uint_as_float(tf32r(Ws[i]));
    Wtc[i] = __uint_as_float(tf32r(Wc[i]));
}

// ---------------- feat via tf32 MMA: A in smem (hi/lo), B via __ldg ----------------
// 256 threads, 32 rows/CTA. Warp w: mt=w&1 (16 rows), nt=w>>1 (32 cols).
// A stored as (hi,lo) float2 (exact split, pad 132). B frags straight from
// pre-rounded global W (L2-hot, L1 reuse across warps). smem = 34 KB -> 6 CTA/SM.
struct FeatSmem {
    float2 A2[32][132];
    int2   xs[32];
};
#define FEAT_SMEM ((int)sizeof(FeatSmem))

__global__ __launch_bounds__(256) void feat_mma_kernel(
    const int* __restrict__ x,
    const float* __restrict__ e0s, const float* __restrict__ e1s,
    const float* __restrict__ Wts, const float* __restrict__ bs, float* __restrict__ outs,
    const float* __restrict__ e0c, const float* __restrict__ e1c,
    const float* __restrict__ Wtc, const float* __restrict__ bc, float* __restrict__ outc)
{
    extern __shared__ char smem_raw[];
    FeatSmem& S = *reinterpret_cast<FeatSmem*>(smem_raw);

    const int halfgrid = N_SRC / 32;
    const bool is_sim = blockIdx.x < halfgrid;
    const int  blk    = is_sim ? blockIdx.x : blockIdx.x - halfgrid;
    const float* emb0 = is_sim ? e0s : e0c;
    const float* emb1 = is_sim ? e1s : e1c;
    const float* Wt   = is_sim ? Wts : Wtc;
    const float* b    = is_sim ? bs  : bc;
    float*       out  = is_sim ? outs : outc;

    const int base = blk * 32;
    const int tid = threadIdx.x;

    if (tid < 32) S.xs[tid] = ((const int2*)x)[base + tid];
    __syncthreads();

    // ---- gather A (32 rows) with exact hi/lo tf32 split ----
    {
        const int k = tid & 127;
        const int rbase = (tid >> 7) * 16;
#pragma unroll
        for (int i = 0; i < 16; i++) {
            const int r = rbase + i;
            const float v = (k < 32) ? emb0[S.xs[r].x * 32 + k]
                                     : emb1[S.xs[r].y * 96 + (k - 32)];
            const uint32_t hb = tf32r(v);
            const float hf = __uint_as_float(hb);
            const uint32_t lb = tf32r(v - hf);
            S.A2[r][k] = make_float2(hf, __uint_as_float(lb));
        }
    }
    __syncthreads();

    // ---- mainloop ----
    const int lane = tid & 31, w = tid >> 5;
    const int mt = w & 1, nt = w >> 1;
    const int gid = lane >> 2, tig = lane & 3;
    const int rA0 = mt * 16 + gid;
    const int rA1 = rA0 + 8;

    float acc[4][4];
#pragma unroll
    for (int s = 0; s < 4; s++)
#pragma unroll
        for (int i = 0; i < 4; i++) acc[s][i] = 0.f;

#pragma unroll
    for (int kc = 0; kc < 16; kc++) {
        const int k0 = kc * 8;
        const float2 fa0 = S.A2[rA0][k0 + tig];
        const float2 fa1 = S.A2[rA1][k0 + tig];
        const float2 fa2 = S.A2[rA0][k0 + tig + 4];
        const float2 fa3 = S.A2[rA1][k0 + tig + 4];
        const uint32_t a0h = __float_as_uint(fa0.x), a0l = __float_as_uint(fa0.y);
        const uint32_t a1h = __float_as_uint(fa1.x), a1l = __float_as_uint(fa1.y);
        const uint32_t a2h = __float_as_uint(fa2.x), a2l = __float_as_uint(fa2.y);
        const uint32_t a3h = __float_as_uint(fa3.x), a3l = __float_as_uint(fa3.y);
#pragma unroll
        for (int sub = 0; sub < 4; sub++) {
            const int n = nt * 32 + sub * 8 + gid;
            const uint32_t b0 = __float_as_uint(__ldg(&Wt[(k0 + tig) * H + n]));
            const uint32_t b1 = __float_as_uint(__ldg(&Wt[(k0 + tig + 4) * H + n]));
            mma_tf32(acc[sub][0], acc[sub][1], acc[sub][2], acc[sub][3],
                     a0h, a1h, a2h, a3h, b0, b1);
            mma_tf32(acc[sub][0], acc[sub][1], acc[sub][2], acc[sub][3],
                     a0l, a1l, a2l, a3l, b0, b1);
        }
    }

    // ---- epilogue: + bias, direct STG.64 ----
#pragma unroll
    for (int sub = 0; sub < 4; sub++) {
        const int n = nt * 32 + sub * 8 + 2 * tig;
        const float2 bv = *(const float2*)&b[n];
        float2 r0 = make_float2(acc[sub][0] + bv.x, acc[sub][1] + bv.y);
        float2 r1 = make_float2(acc[sub][2] + bv.x, acc[sub][3] + bv.y);
        *(float2*)&out[(base + rA0) * H + n] = r0;
        *(float2*)&out[(base + rA1) * H + n] = r1;
    }
}

// ---------------- co-attention pool (R6 version) ----------------
__global__ __launch_bounds__(256) void attn_kernel(
    const float* __restrict__ feat_sim, const float* __restrict__ feat_cor,
    const int* __restrict__ neigh_sim, const int* __restrict__ neigh_cor,
    float* __restrict__ rst_sim, float* __restrict__ rst_cor)
{
    __shared__ float Ds[32][132];
    __shared__ float Qs[32][132];
    __shared__ float Es[32][33];
    __shared__ float invcol[32];
    __shared__ float invrow[32];
    __shared__ float wv[32];
    __shared__ float vv[32];
    __shared__ float coef[32];
    __shared__ float O[3 * H];

    const bool is_sim = blockIdx.x < N_DST;
    const int  node   = is_sim ? blockIdx.x : (blockIdx.x - N_DST);
    const float* feat = is_sim ? feat_sim : feat_cor;
    const int* idxD = is_sim ? neigh_cor : neigh_sim;   // sim: D = nf_cor
    const int* idxQ = is_sim ? neigh_sim : neigh_cor;
    float*     rst  = is_sim ? rst_sim : rst_cor;

    const int tid = threadIdx.x;
    const int lane = tid & 31;
    const int w = tid >> 5;

#pragma unroll
    for (int i = 0; i < 4; i++) {
        const int r = w * 4 + i;
        const int id = idxD[node * 32 + r];
        ((float4*)&Ds[r][0])[lane] = ((const float4*)feat)[id * 32 + lane];
        const int iq = idxQ[node * 32 + r];
        ((float4*)&Qs[r][0])[lane] = ((const float4*)feat)[iq * 32 + lane];
    }
    __syncthreads();

    {
        const int mt = w & 1;
        const int nt = w >> 1;
        const int gid = lane >> 2;
        const int tig = lane & 3;
        const int rA0 = mt * 16 + gid;
        const int rA1 = rA0 + 8;
        const int cn  = nt * 8 + gid;

        float c0 = 0.f, c1 = 0.f, c2 = 0.f, c3 = 0.f;
#pragma unroll
        for (int kc = 0; kc < 16; kc++) {
            const int k0 = kc * 8;
            const uint32_t a0 = tf32r(Ds[rA0][k0 + tig]);
            const uint32_t a1 = tf32r(Ds[rA1][k0 + tig]);
            const uint32_t a2 = tf32r(Ds[rA0][k0 + tig + 4]);
            const uint32_t a3 = tf32r(Ds[rA1][k0 + tig + 4]);
            const uint32_t b0 = tf32r(Qs[cn][k0 + tig]);
            const uint32_t b1 = tf32r(Qs[cn][k0 + tig + 4]);
            mma_tf32(c0, c1, c2, c3, a0, a1, a2, a3, b0, b1);
        }
        const int ec = nt * 8 + 2 * tig;
        Es[rA0][ec]     = __expf(c0);
        Es[rA0][ec + 1] = __expf(c1);
        Es[rA1][ec]     = __expf(c2);
        Es[rA1][ec + 1] = __expf(c3);
    }
    __syncthreads();

    if (w == 0) {
        const int m = lane;
        float s = 0.f;
#pragma unroll
        for (int k = 0; k < 32; k++) s += Es[m][k];
        invrow[m] = __frcp_rn(s);
    } else if (w == 1) {
        const int k = lane;
        float s = 0.f;
#pragma unroll
        for (int m = 0; m < 32; m++) s += Es[m][k];
        invcol[k] = __frcp_rn(s);
    }
    __syncthreads();

    if (w == 0) {
        const int m = lane;
        float s = 0.f;
#pragma unroll
        for (int k = 0; k < 32; k++) s += Es[m][k] * invcol[k];
        wv[m] = s;
        coef[m] = s * invrow[m];
    }
    __syncthreads();

    if (w == 1) {
        const int k = lane;
        float s = 0.f;
#pragma unroll
        for (int m = 0; m < 32; m++) s += coef[m] * Es[m][k];
        vv[k] = s;
    }
    __syncthreads();

    if (tid < 128) {
        const int h = tid;
        float sq = 0.f, scq = 0.f;
#pragma unroll
        for (int m = 0; m < 32; m++) {
            const float q = Qs[m][h];
            sq  += q;
            scq += vv[m] * q;
        }
        O[h]         = sq;
        O[2 * H + h] = scq;
    } else {
        const int h = tid - 128;
        float sdw = 0.f;
#pragma unroll
        for (int m = 0; m < 32; m++) sdw += wv[m] * Ds[m][h];
        O[H + h] = sdw;
    }
    __syncthreads();

    if (tid < 128) {
        const int h = tid;
        const float r = (O[3 * h] + O[3 * h + 1] + O[3 * h + 2]) * (1.f / 96.f);
        rst[node * H + h] = feat[node * H + h] + r;
    }
}

// ---------------- precompute: H1 = Wos@Ws2c, H2 = Woc@Wc2s ----------------
__global__ __launch_bounds__(128) void pre1_kernel(
    const float* __restrict__ Wos, const float* __restrict__ Ws2c,
    const float* __restrict__ Woc, const float* __restrict__ Wc2s,
    float* __restrict__ H1, float* __restrict__ H2)
{
    const bool first = blockIdx.x < H;
    const int r = first ? blockIdx.x : blockIdx.x - H;
    const float* U = first ? Wos : Woc;
    const float* V = first ? Ws2c : Wc2s;
    float* Oo = first ? H1 : H2;
    const int j = threadIdx.x;
    float s = 0.f;
#pragma unroll 4
    for (int k = 0; k < H; k++) s += U[r * H + k] * V[k * H + j];
    Oo[r * H + j] = s;
}

// ---------------- precompute: M quadrants ----------------
__global__ __launch_bounds__(128) void pre2_kernel(
    const float* __restrict__ Wos, const float* __restrict__ Woc,
    const float* __restrict__ Ws2c, const float* __restrict__ Wc2s,
    const float* __restrict__ H1, const float* __restrict__ H2,
    float* __restrict__ M)
{
    const int quad = blockIdx.x >> 7;
    const int r = blockIdx.x & 127;
    const int j = threadIdx.x;
    if (quad == 0) {
        float s = 0.f;
#pragma unroll 4
        for (int k = 0; k < H; k++) s += H1[r * H + k] * Wc2s[k * H + j];
        M[r * 256 + j] = 0.34f * Wos[r * H + j] + 0.165f * s;
    } else if (quad == 1) {
        M[r * 256 + 128 + j] = 0.495f * H1[r * H + j];
    } else if (quad == 2) {
        M[(128 + r) * 256 + j] = 0.495f * H2[r * H + j];
    } else {
        float s = 0.f;
#pragma unroll 4
        for (int k = 0; k < H; k++) s += H2[r * H + k] * Ws2c[k * H + j];
        M[(128 + r) * 256 + 128 + j] = 0.34f * Woc[r * H + j] + 0.165f * s;
    }
}

// ---------------- precompute: fused bias c ----------------
__global__ __launch_bounds__(128) void pre3_kernel(
    const float* __restrict__ bos, const float* __restrict__ boc,
    const float* __restrict__ Ws2c, const float* __restrict__ Wc2s,
    float* __restrict__ c)
{
    __shared__ float u[H], v[H];
    const int j = threadIdx.x;
    float su = 0.f, sv = 0.f;
    for (int k = 0; k < H; k++) {
        su += bos[k] * Ws2c[k * H + j];
        sv += boc[k] * Wc2s[k * H + j];
    }
    u[j] = su; v[j] = sv;
    __syncthreads();
    float t1 = 0.f, t2 = 0.f;
    for (int k = 0; k < H; k++) {
        t1 += u[k] * Wc2s[k * H + j];
        t2 += v[k] * Ws2c[k * H + j];
    }
    c[j]       = 0.34f * bos[j] + 0.165f * t1 + 0.495f * v[j];
    c[128 + j] = 0.34f * boc[j] + 0.165f * t2 + 0.495f * u[j];
}

// ---------------- fused final GEMM ----------------
__global__ __launch_bounds__(128) void mix_kernel(
    const float* __restrict__ rst_sim, const float* __restrict__ rst_cor,
    const float* __restrict__ M, const float* __restrict__ c,
    float* __restrict__ out)
{
    __shared__ float xb[256][34];
    const int base = blockIdx.x * 32;
    const int tid = threadIdx.x;

    for (int kk = tid; kk < 256; kk += 128) {
        const float* src = (kk < 128) ? (rst_sim + (size_t)base * H + kk)
                                      : (rst_cor + (size_t)base * H + (kk - 128));
#pragma unroll 4
        for (int r = 0; r < 32; r++) xb[kk][r] = src[r * H];
    }
    __syncthreads();

    const int j0 = tid;
    const int j1 = tid + 128;
    ULL acc0[16], acc1[16];
#pragma unroll
    for (int rp = 0; rp < 16; rp++) { acc0[rp] = 0ULL; acc1[rp] = 0ULL; }

#pragma unroll 2
    for (int k = 0; k < 256; k++) {
        const float w0 = M[k * 256 + j0];
        const float w1 = M[k * 256 + j1];
        const ULL wd0 = pk2(w0, w0);
        const ULL wd1 = pk2(w1, w1);
        const ULL* xp = (const ULL*)&xb[k][0];
#pragma unroll
        for (int rp = 0; rp < 16; rp++) {
            const ULL xv = xp[rp];
            ffma2(acc0[rp], xv, wd0);
            ffma2(acc1[rp], xv, wd1);
        }
    }

    const float c0 = c[j0], c1 = c[j1];
    float* o0 = out + j0;
    float* o1 = out + (size_t)N_DST * H + tid;
#pragma unroll
    for (int rp = 0; rp < 16; rp++) {
        const float2 f0 = upk2(acc0[rp]);
        const float2 f1 = upk2(acc1[rp]);
        o0[(size_t)(base + 2 * rp + 0) * H] = f0.x + c0;
        o0[(size_t)(base + 2 * rp + 1) * H] = f0.y + c0;
        o1[(size_t)(base + 2 * rp + 0) * H] = f1.x + c1;
        o1[(size_t)(base + 2 * rp + 1) * H] = f1.y + c1;
    }
}

// ---------------- launch ----------------
extern "C" void kernel_launch(void* const* d_in, const int* in_sizes, int n_in,
                              void* d_out, int out_size)
{
    const int*   x         = (const int*)d_in[0];
    const int*   neigh_sim = (const int*)d_in[1];
    const int*   neigh_cor = (const int*)d_in[2];
    const float* emb0_sim  = (const float*)d_in[3];
    const float* emb1_sim  = (const float*)d_in[4];
    const float* emb0_cor  = (const float*)d_in[5];
    const float* emb1_cor  = (const float*)d_in[6];
    const float* W_in_sim  = (const float*)d_in[7];
    const float* b_in_sim  = (const float*)d_in[8];
    const float* W_in_cor  = (const float*)d_in[9];
    const float* b_in_cor  = (const float*)d_in[10];
    const float* W_out_sim = (const float*)d_in[11];
    const float* b_out_sim = (const float*)d_in[12];
    const float* W_out_cor = (const float*)d_in[13];
    const float* b_out_cor = (const float*)d_in[14];
    const float* W_sim2cor = (const float*)d_in[15];
    const float* W_cor2sim = (const float*)d_in[16];

    float *feat_sim, *feat_cor, *rst_sim, *rst_cor, *Wts, *Wtc, *H1, *H2, *M, *c;
    cudaGetSymbolAddress((void**)&feat_sim, g_feat_sim);
    cudaGetSymbolAddress((void**)&feat_cor, g_feat_cor);
    cudaGetSymbolAddress((void**)&rst_sim,  g_rst_sim);
    cudaGetSymbolAddress((void**)&rst_cor,  g_rst_cor);
    cudaGetSymbolAddress((void**)&Wts,      g_Wts);
    cudaGetSymbolAddress((void**)&Wtc,      g_Wtc);
    cudaGetSymbolAddress((void**)&H1,       g_H1);
    cudaGetSymbolAddress((void**)&H2,       g_H2);
    cudaGetSymbolAddress((void**)&M,        g_M);
    cudaGetSymbolAddress((void**)&c,        g_c);

    float* out = (float*)d_out;

    cudaFuncSetAttribute(feat_mma_kernel, cudaFuncAttributeMaxDynamicSharedMemorySize, FEAT_SMEM);

    preW_kernel<<<H * H / 256, 256>>>(W_in_sim, W_in_cor, Wts, Wtc);
    pre1_kernel<<<2 * H, 128>>>(W_out_sim, W_sim2cor, W_out_cor, W_cor2sim, H1, H2);
    pre2_kernel<<<4 * H, 128>>>(W_out_sim, W_out_cor, W_sim2cor, W_cor2sim, H1, H2, M);
    pre3_kernel<<<1, 128>>>(b_out_sim, b_out_cor, W_sim2cor, W_cor2sim, c);

    feat_mma_kernel<<<2 * (N_SRC / 32), 256, FEAT_SMEM>>>(x,
        emb0_sim, emb1_sim, Wts, b_in_sim, feat_sim,
        emb0_cor, emb1_cor, Wtc, b_in_cor, feat_cor);

    attn_kernel<<<2 * N_DST, 256>>>(feat_sim, feat_cor, neigh_sim, neigh_cor,
                                    rst_sim, rst_cor);

    mix_kernel<<<N_DST / 32, 128>>>(rst_sim, rst_cor, M, c, out);
}

// round 13
// speedup vs baseline: 1.1775x; 1.0446x over previous
#include <cuda_runtime.h>
#include <cstdint>

#define N_SRC 65536
#define N_DST 8192
#define MAXN  32
#define H     128

typedef unsigned long long ULL;

// ---------------- f32x2 helpers ----------------
__device__ __forceinline__ void ffma2(ULL& d, ULL a, ULL b) {
    asm("fma.rn.f32x2 %0, %1, %2, %3;" : "=l"(d) : "l"(a), "l"(b), "l"(d));
}
__device__ __forceinline__ ULL pk2(float x, float y) {
    ULL r; asm("mov.b64 %0, {%1, %2};" : "=l"(r) : "f"(x), "f"(y)); return r;
}
__device__ __forceinline__ float2 upk2(ULL v) {
    float2 f; asm("mov.b64 {%0, %1}, %2;" : "=f"(f.x), "=f"(f.y) : "l"(v)); return f;
}

// ---------------- tf32 mma helpers ----------------
__device__ __forceinline__ uint32_t tf32r(float x) {
    uint32_t r; asm("cvt.rna.tf32.f32 %0, %1;" : "=r"(r) : "f"(x)); return r;
}
__device__ __forceinline__ void mma_tf32(float& d0, float& d1, float& d2, float& d3,
    uint32_t a0, uint32_t a1, uint32_t a2, uint32_t a3, uint32_t b0, uint32_t b1)
{
    asm volatile("mma.sync.aligned.m16n8k8.row.col.f32.tf32.tf32.f32 "
        "{%0,%1,%2,%3}, {%4,%5,%6,%7}, {%8,%9}, {%0,%1,%2,%3};"
        : "+f"(d0), "+f"(d1), "+f"(d2), "+f"(d3)
        : "r"(a0), "r"(a1), "r"(a2), "r"(a3), "r"(b0), "r"(b1));
}

// ---------------- scratch ----------------
__device__ __align__(16) float g_feat_sim[N_SRC * H];
__device__ __align__(16) float g_feat_cor[N_SRC * H];
__device__ __align__(16) float g_rst_sim[N_DST * H];
__device__ __align__(16) float g_rst_cor[N_DST * H];
__device__ __align__(16) float g_Wts[H * H];
__device__ __align__(16) float g_Wtc[H * H];
__device__ __align__(16) float g_H1[H * H];
__device__ __align__(16) float g_H2[H * H];
__device__ __align__(16) float g_M[256 * 256];
__device__ __align__(16) float g_c[256];

// ---------------- preA: fused preW + pre1 + pre3 ----------------
// blocks [0,256): H1 = Wos@Ws2c, H2 = Woc@Wc2s  (pre1)
// blocks [256,384): tf32-round W_in into g_Wts/g_Wtc (preW)
// block 384: fused bias c (pre3, unrolled)
__global__ __launch_bounds__(128) void preA_kernel(
    const float* __restrict__ Wos, const float* __restrict__ Ws2c,
    const float* __restrict__ Woc, const float* __restrict__ Wc2s,
    const float* __restrict__ Wis, const float* __restrict__ Wic,
    const float* __restrict__ bos, const float* __restrict__ boc,
    float* __restrict__ H1, float* __restrict__ H2,
    float* __restrict__ Wts, float* __restrict__ Wtc,
    float* __restrict__ c)
{
    const int blk = blockIdx.x;
    const int j = threadIdx.x;

    if (blk < 256) {
        const bool first = blk < H;
        const int r = first ? blk : blk - H;
        const float* U = first ? Wos : Woc;
        const float* V = first ? Ws2c : Wc2s;
        float* Oo = first ? H1 : H2;
        float s = 0.f;
#pragma unroll 8
        for (int k = 0; k < H; k++) s += U[r * H + k] * V[k * H + j];
        Oo[r * H + j] = s;
    } else if (blk < 384) {
        const int i = (blk - 256) * 128 + j;
        Wts[i] = __uint_as_float(tf32r(Wis[i]));
        Wtc[i] = __uint_as_float(tf32r(Wic[i]));
    } else {
        __shared__ float u[H], v[H];
        float su = 0.f, sv = 0.f;
#pragma unroll 8
        for (int k = 0; k < H; k++) {
            su += bos[k] * Ws2c[k * H + j];
            sv += boc[k] * Wc2s[k * H + j];
        }
        u[j] = su; v[j] = sv;
        __syncthreads();
        float t1 = 0.f, t2 = 0.f;
#pragma unroll 8
        for (int k = 0; k < H; k++) {
            t1 += u[k] * Wc2s[k * H + j];
            t2 += v[k] * Ws2c[k * H + j];
        }
        c[j]       = 0.34f * bos[j] + 0.165f * t1 + 0.495f * v[j];
        c[128 + j] = 0.34f * boc[j] + 0.165f * t2 + 0.495f * u[j];
    }
}

// ---------------- pre2: M quadrants ----------------
__global__ __launch_bounds__(128) void pre2_kernel(
    const float* __restrict__ Wos, const float* __restrict__ Woc,
    const float* __restrict__ Ws2c, const float* __restrict__ Wc2s,
    const float* __restrict__ H1, const float* __restrict__ H2,
    float* __restrict__ M)
{
    const int quad = blockIdx.x >> 7;
    const int r = blockIdx.x & 127;
    const int j = threadIdx.x;
    if (quad == 0) {
        float s = 0.f;
#pragma unroll 8
        for (int k = 0; k < H; k++) s += H1[r * H + k] * Wc2s[k * H + j];
        M[r * 256 + j] = 0.34f * Wos[r * H + j] + 0.165f * s;
    } else if (quad == 1) {
        M[r * 256 + 128 + j] = 0.495f * H1[r * H + j];
    } else if (quad == 2) {
        M[(128 + r) * 256 + j] = 0.495f * H2[r * H + j];
    } else {
        float s = 0.f;
#pragma unroll 8
        for (int k = 0; k < H; k++) s += H2[r * H + k] * Ws2c[k * H + j];
        M[(128 + r) * 256 + 128 + j] = 0.34f * Woc[r * H + j] + 0.165f * s;
    }
}

// ---------------- feat via tf32 MMA: A in smem (hi/lo), B via __ldg ----------------
struct FeatSmem {
    float2 A2[32][132];
    int2   xs[32];
};
#define FEAT_SMEM ((int)sizeof(FeatSmem))

__global__ __launch_bounds__(256) void feat_mma_kernel(
    const int* __restrict__ x,
    const float* __restrict__ e0s, const float* __restrict__ e1s,
    const float* __restrict__ Wts, const float* __restrict__ bs, float* __restrict__ outs,
    const float* __restrict__ e0c, const float* __restrict__ e1c,
    const float* __restrict__ Wtc, const float* __restrict__ bc, float* __restrict__ outc)
{
    extern __shared__ char smem_raw[];
    FeatSmem& S = *reinterpret_cast<FeatSmem*>(smem_raw);

    const int halfgrid = N_SRC / 32;
    const bool is_sim = blockIdx.x < halfgrid;
    const int  blk    = is_sim ? blockIdx.x : blockIdx.x - halfgrid;
    const float* emb0 = is_sim ? e0s : e0c;
    const float* emb1 = is_sim ? e1s : e1c;
    const float* Wt   = is_sim ? Wts : Wtc;
    const float* b    = is_sim ? bs  : bc;
    float*       out  = is_sim ? outs : outc;

    const int base = blk * 32;
    const int tid = threadIdx.x;

    if (tid < 32) S.xs[tid] = ((const int2*)x)[base + tid];
    __syncthreads();

    {
        const int k = tid & 127;
        const int rbase = (tid >> 7) * 16;
#pragma unroll
        for (int i = 0; i < 16; i++) {
            const int r = rbase + i;
            const float v = (k < 32) ? emb0[S.xs[r].x * 32 + k]
                                     : emb1[S.xs[r].y * 96 + (k - 32)];
            const uint32_t hb = tf32r(v);
            const float hf = __uint_as_float(hb);
            const uint32_t lb = tf32r(v - hf);
            S.A2[r][k] = make_float2(hf, __uint_as_float(lb));
        }
    }
    __syncthreads();

    const int lane = tid & 31, w = tid >> 5;
    const int mt = w & 1, nt = w >> 1;
    const int gid = lane >> 2, tig = lane & 3;
    const int rA0 = mt * 16 + gid;
    const int rA1 = rA0 + 8;

    float acc[4][4];
#pragma unroll
    for (int s = 0; s < 4; s++)
#pragma unroll
        for (int i = 0; i < 4; i++) acc[s][i] = 0.f;

#pragma unroll
    for (int kc = 0; kc < 16; kc++) {
        const int k0 = kc * 8;
        const float2 fa0 = S.A2[rA0][k0 + tig];
        const float2 fa1 = S.A2[rA1][k0 + tig];
        const float2 fa2 = S.A2[rA0][k0 + tig + 4];
        const float2 fa3 = S.A2[rA1][k0 + tig + 4];
        const uint32_t a0h = __float_as_uint(fa0.x), a0l = __float_as_uint(fa0.y);
        const uint32_t a1h = __float_as_uint(fa1.x), a1l = __float_as_uint(fa1.y);
        const uint32_t a2h = __float_as_uint(fa2.x), a2l = __float_as_uint(fa2.y);
        const uint32_t a3h = __float_as_uint(fa3.x), a3l = __float_as_uint(fa3.y);
#pragma unroll
        for (int sub = 0; sub < 4; sub++) {
            const int n = nt * 32 + sub * 8 + gid;
            const uint32_t b0 = __float_as_uint(__ldg(&Wt[(k0 + tig) * H + n]));
            const uint32_t b1 = __float_as_uint(__ldg(&Wt[(k0 + tig + 4) * H + n]));
            mma_tf32(acc[sub][0], acc[sub][1], acc[sub][2], acc[sub][3],
                     a0h, a1h, a2h, a3h, b0, b1);
            mma_tf32(acc[sub][0], acc[sub][1], acc[sub][2], acc[sub][3],
                     a0l, a1l, a2l, a3l, b0, b1);
        }
    }

#pragma unroll
    for (int sub = 0; sub < 4; sub++) {
        const int n = nt * 32 + sub * 8 + 2 * tig;
        const float2 bv = *(const float2*)&b[n];
        float2 r0 = make_float2(acc[sub][0] + bv.x, acc[sub][1] + bv.y);
        float2 r1 = make_float2(acc[sub][2] + bv.x, acc[sub][3] + bv.y);
        *(float2*)&out[(base + rA0) * H + n] = r0;
        *(float2*)&out[(base + rA1) * H + n] = r1;
    }
}

// ---------------- co-attention pool (R6 math; Es/O overlaid, 6 CTA/SM) ----------------
__global__ __launch_bounds__(256, 6) void attn_kernel(
    const float* __restrict__ feat_sim, const float* __restrict__ feat_cor,
    const int* __restrict__ neigh_sim, const int* __restrict__ neigh_cor,
    float* __restrict__ rst_sim, float* __restrict__ rst_cor)
{
    __shared__ float Ds[32][132];
    __shared__ float Qs[32][132];
    __shared__ float EsO[32 * 33];   // Es[m][k] = EsO[m*33+k]; later reused as O[0..383]
    __shared__ float invcol[32];
    __shared__ float invrow[32];
    __shared__ float wv[32];
    __shared__ float vv[32];
    __shared__ float coef[32];
#define ES(m_, k_) EsO[(m_) * 33 + (k_)]

    const bool is_sim = blockIdx.x < N_DST;
    const int  node   = is_sim ? blockIdx.x : (blockIdx.x - N_DST);
    const float* feat = is_sim ? feat_sim : feat_cor;
    const int* idxD = is_sim ? neigh_cor : neigh_sim;   // sim: D = nf_cor
    const int* idxQ = is_sim ? neigh_sim : neigh_cor;
    float*     rst  = is_sim ? rst_sim : rst_cor;

    const int tid = threadIdx.x;
    const int lane = tid & 31;
    const int w = tid >> 5;

#pragma unroll
    for (int i = 0; i < 4; i++) {
        const int r = w * 4 + i;
        const int id = idxD[node * 32 + r];
        ((float4*)&Ds[r][0])[lane] = ((const float4*)feat)[id * 32 + lane];
        const int iq = idxQ[node * 32 + r];
        ((float4*)&Qs[r][0])[lane] = ((const float4*)feat)[iq * 32 + lane];
    }
    __syncthreads();

    {
        const int mt = w & 1;
        const int nt = w >> 1;
        const int gid = lane >> 2;
        const int tig = lane & 3;
        const int rA0 = mt * 16 + gid;
        const int rA1 = rA0 + 8;
        const int cn  = nt * 8 + gid;

        float c0 = 0.f, c1 = 0.f, c2 = 0.f, c3 = 0.f;
#pragma unroll
        for (int kc = 0; kc < 16; kc++) {
            const int k0 = kc * 8;
            const uint32_t a0 = tf32r(Ds[rA0][k0 + tig]);
            const uint32_t a1 = tf32r(Ds[rA1][k0 + tig]);
            const uint32_t a2 = tf32r(Ds[rA0][k0 + tig + 4]);
            const uint32_t a3 = tf32r(Ds[rA1][k0 + tig + 4]);
            const uint32_t b0 = tf32r(Qs[cn][k0 + tig]);
            const uint32_t b1 = tf32r(Qs[cn][k0 + tig + 4]);
            mma_tf32(c0, c1, c2, c3, a0, a1, a2, a3, b0, b1);
        }
        const int ec = nt * 8 + 2 * tig;
        ES(rA0, ec)     = __expf(c0);
        ES(rA0, ec + 1) = __expf(c1);
        ES(rA1, ec)     = __expf(c2);
        ES(rA1, ec + 1) = __expf(c3);
    }
    __syncthreads();

    if (w == 0) {
        const int m = lane;
        float s = 0.f;
#pragma unroll
        for (int k = 0; k < 32; k++) s += ES(m, k);
        invrow[m] = __frcp_rn(s);
    } else if (w == 1) {
        const int k = lane;
        float s = 0.f;
#pragma unroll
        for (int m = 0; m < 32; m++) s += ES(m, k);
        invcol[k] = __frcp_rn(s);
    }
    __syncthreads();

    if (w == 0) {
        const int m = lane;
        float s = 0.f;
#pragma unroll
        for (int k = 0; k < 32; k++) s += ES(m, k) * invcol[k];
        wv[m] = s;
        coef[m] = s * invrow[m];
    }
    __syncthreads();

    float myw = 0.f, myv = 0.f;   // carry wv/vv values before EsO is overwritten
    if (w == 1) {
        const int k = lane;
        float s = 0.f;
#pragma unroll
        for (int m = 0; m < 32; m++) s += coef[m] * ES(m, k);
        vv[k] = s;
    }
    __syncthreads();
    // ---- EsO now reused as O[0..383] (Es fully consumed above) ----
    float* O = EsO;

    if (tid < 128) {
        const int h = tid;
        float sq = 0.f, scq = 0.f;
#pragma unroll
        for (int m = 0; m < 32; m++) {
            const float q = Qs[m][h];
            sq  += q;
            scq += vv[m] * q;
        }
        O[h]         = sq;
        O[2 * H + h] = scq;
    } else {
        const int h = tid - 128;
        float sdw = 0.f;
#pragma unroll
        for (int m = 0; m < 32; m++) sdw += wv[m] * Ds[m][h];
        O[H + h] = sdw;
    }
    __syncthreads();

    if (tid < 128) {
        const int h = tid;
        const float r = (O[3 * h] + O[3 * h + 1] + O[3 * h + 2]) * (1.f / 96.f);
        rst[node * H + h] = feat[node * H + h] + r;
    }
    (void)myw; (void)myv;
#undef ES
}

// ---------------- fused final GEMM ----------------
__global__ __launch_bounds__(128) void mix_kernel(
    const float* __restrict__ rst_sim, const float* __restrict__ rst_cor,
    const float* __restrict__ M, const float* __restrict__ c,
    float* __restrict__ out)
{
    __shared__ float xb[256][34];
    const int base = blockIdx.x * 32;
    const int tid = threadIdx.x;

    for (int kk = tid; kk < 256; kk += 128) {
        const float* src = (kk < 128) ? (rst_sim + (size_t)base * H + kk)
                                      : (rst_cor + (size_t)base * H + (kk - 128));
#pragma unroll 4
        for (int r = 0; r < 32; r++) xb[kk][r] = src[r * H];
    }
    __syncthreads();

    const int j0 = tid;
    const int j1 = tid + 128;
    ULL acc0[16], acc1[16];
#pragma unroll
    for (int rp = 0; rp < 16; rp++) { acc0[rp] = 0ULL; acc1[rp] = 0ULL; }

#pragma unroll 2
    for (int k = 0; k < 256; k++) {
        const float w0 = M[k * 256 + j0];
        const float w1 = M[k * 256 + j1];
        const ULL wd0 = pk2(w0, w0);
        const ULL wd1 = pk2(w1, w1);
        const ULL* xp = (const ULL*)&xb[k][0];
#pragma unroll
        for (int rp = 0; rp < 16; rp++) {
            const ULL xv = xp[rp];
            ffma2(acc0[rp], xv, wd0);
            ffma2(acc1[rp], xv, wd1);
        }
    }

    const float c0 = c[j0], c1 = c[j1];
    float* o0 = out + j0;
    float* o1 = out + (size_t)N_DST * H + tid;
#pragma unroll
    for (int rp = 0; rp < 16; rp++) {
        const float2 f0 = upk2(acc0[rp]);
        const float2 f1 = upk2(acc1[rp]);
        o0[(size_t)(base + 2 * rp + 0) * H] = f0.x + c0;
        o0[(size_t)(base + 2 * rp + 1) * H] = f0.y + c0;
        o1[(size_t)(base + 2 * rp + 0) * H] = f1.x + c1;
        o1[(size_t)(base + 2 * rp + 1) * H] = f1.y + c1;
    }
}

// ---------------- launch ----------------
extern "C" void kernel_launch(void* const* d_in, const int* in_sizes, int n_in,
                              void* d_out, int out_size)
{
    const int*   x         = (const int*)d_in[0];
    const int*   neigh_sim = (const int*)d_in[1];
    const int*   neigh_cor = (const int*)d_in[2];
    const float* emb0_sim  = (const float*)d_in[3];
    const float* emb1_sim  = (const float*)d_in[4];
    const float* emb0_cor  = (const float*)d_in[5];
    const float* emb1_cor  = (const float*)d_in[6];
    const float* W_in_sim  = (const float*)d_in[7];
    const float* b_in_sim  = (const float*)d_in[8];
    const float* W_in_cor  = (const float*)d_in[9];
    const float* b_in_cor  = (const float*)d_in[10];
    const float* W_out_sim = (const float*)d_in[11];
    const float* b_out_sim = (const float*)d_in[12];
    const float* W_out_cor = (const float*)d_in[13];
    const float* b_out_cor = (const float*)d_in[14];
    const float* W_sim2cor = (const float*)d_in[15];
    const float* W_cor2sim = (const float*)d_in[16];

    float *feat_sim, *feat_cor, *rst_sim, *rst_cor, *Wts, *Wtc, *H1, *H2, *M, *c;
    cudaGetSymbolAddress((void**)&feat_sim, g_feat_sim);
    cudaGetSymbolAddress((void**)&feat_cor, g_feat_cor);
    cudaGetSymbolAddress((void**)&rst_sim,  g_rst_sim);
    cudaGetSymbolAddress((void**)&rst_cor,  g_rst_cor);
    cudaGetSymbolAddress((void**)&Wts,      g_Wts);
    cudaGetSymbolAddress((void**)&Wtc,      g_Wtc);
    cudaGetSymbolAddress((void**)&H1,       g_H1);
    cudaGetSymbolAddress((void**)&H2,       g_H2);
    cudaGetSymbolAddress((void**)&M,        g_M);
    cudaGetSymbolAddress((void**)&c,        g_c);

    float* out = (float*)d_out;

    cudaFuncSetAttribute(feat_mma_kernel, cudaFuncAttributeMaxDynamicSharedMemorySize, FEAT_SMEM);

    preA_kernel<<<385, 128>>>(W_out_sim, W_sim2cor, W_out_cor, W_cor2sim,
                              W_in_sim, W_in_cor, b_out_sim, b_out_cor,
                              H1, H2, Wts, Wtc, c);
    pre2_kernel<<<4 * H, 128>>>(W_out_sim, W_out_cor, W_sim2cor, W_cor2sim, H1, H2, M);

    feat_mma_kernel<<<2 * (N_SRC / 32), 256, FEAT_SMEM>>>(x,
        emb0_sim, emb1_sim, Wts, b_in_sim, feat_sim,
        emb0_cor, emb1_cor, Wtc, b_in_cor, feat_cor);

    attn_kernel<<<2 * N_DST, 256>>>(feat_sim, feat_cor, neigh_sim, neigh_cor,
                                    rst_sim, rst_cor);

    mix_kernel<<<N_DST / 32, 128>>>(rst_sim, rst_cor, M, c, out);
}

// round 17
// speedup vs baseline: 1.3477x; 1.1445x over previous
#include <cuda_runtime.h>
#include <cuda_fp16.h>
#include <cstdint>

#define N_SRC 65536
#define N_DST 8192
#define MAXN  32
#define H     128

typedef unsigned long long ULL;

// ---------------- f32x2 helpers ----------------
__device__ __forceinline__ void ffma2(ULL& d, ULL a, ULL b) {
    asm("fma.rn.f32x2 %0, %1, %2, %3;" : "=l"(d) : "l"(a), "l"(b), "l"(d));
}
__device__ __forceinline__ ULL pk2(float x, float y) {
    ULL r; asm("mov.b64 %0, {%1, %2};" : "=l"(r) : "f"(x), "f"(y)); return r;
}
__device__ __forceinline__ float2 upk2(ULL v) {
    float2 f; asm("mov.b64 {%0, %1}, %2;" : "=f"(f.x), "=f"(f.y) : "l"(v)); return f;
}

// ---------------- tf32 mma helpers (feat) ----------------
__device__ __forceinline__ uint32_t tf32r(float x) {
    uint32_t r; asm("cvt.rna.tf32.f32 %0, %1;" : "=r"(r) : "f"(x)); return r;
}
__device__ __forceinline__ void mma_tf32(float& d0, float& d1, float& d2, float& d3,
    uint32_t a0, uint32_t a1, uint32_t a2, uint32_t a3, uint32_t b0, uint32_t b1)
{
    asm volatile("mma.sync.aligned.m16n8k8.row.col.f32.tf32.tf32.f32 "
        "{%0,%1,%2,%3}, {%4,%5,%6,%7}, {%8,%9}, {%0,%1,%2,%3};"
        : "+f"(d0), "+f"(d1), "+f"(d2), "+f"(d3)
        : "r"(a0), "r"(a1), "r"(a2), "r"(a3), "r"(b0), "r"(b1));
}

// ---------------- fp16 mma helper (attn L) ----------------
__device__ __forceinline__ void mma_f16(float& d0, float& d1, float& d2, float& d3,
    uint32_t a0, uint32_t a1, uint32_t a2, uint32_t a3, uint32_t b0, uint32_t b1)
{
    asm volatile("mma.sync.aligned.m16n8k16.row.col.f32.f16.f16.f32 "
        "{%0,%1,%2,%3}, {%4,%5,%6,%7}, {%8,%9}, {%0,%1,%2,%3};"
        : "+f"(d0), "+f"(d1), "+f"(d2), "+f"(d3)
        : "r"(a0), "r"(a1), "r"(a2), "r"(a3), "r"(b0), "r"(b1));
}
__device__ __forceinline__ uint32_t packh2(float a, float b) {
    __half2 h = __floats2half2_rn(a, b);
    return *reinterpret_cast<uint32_t*>(&h);
}

// ---------------- scratch ----------------
__device__ __align__(16) float g_feat_sim[N_SRC * H];
__device__ __align__(16) float g_feat_cor[N_SRC * H];
__device__ __align__(16) float g_rst_sim[N_DST * H];
__device__ __align__(16) float g_rst_cor[N_DST * H];
__device__ __align__(16) float g_Wts[H * H];
__device__ __align__(16) float g_Wtc[H * H];
__device__ __align__(16) float g_H1[H * H];
__device__ __align__(16) float g_H2[H * H];
__device__ __align__(16) float g_M[256 * 256];
__device__ __align__(16) float g_c[256];

// ---------------- preA: fused preW + pre1 + pre3 ----------------
__global__ __launch_bounds__(128) void preA_kernel(
    const float* __restrict__ Wos, const float* __restrict__ Ws2c,
    const float* __restrict__ Woc, const float* __restrict__ Wc2s,
    const float* __restrict__ Wis, const float* __restrict__ Wic,
    const float* __restrict__ bos, const float* __restrict__ boc,
    float* __restrict__ H1, float* __restrict__ H2,
    float* __restrict__ Wts, float* __restrict__ Wtc,
    float* __restrict__ c)
{
    const int blk = blockIdx.x;
    const int j = threadIdx.x;

    if (blk < 256) {
        const bool first = blk < H;
        const int r = first ? blk : blk - H;
        const float* U = first ? Wos : Woc;
        const float* V = first ? Ws2c : Wc2s;
        float* Oo = first ? H1 : H2;
        float s = 0.f;
#pragma unroll 8
        for (int k = 0; k < H; k++) s += U[r * H + k] * V[k * H + j];
        Oo[r * H + j] = s;
    } else if (blk < 384) {
        const int i = (blk - 256) * 128 + j;
        Wts[i] = __uint_as_float(tf32r(Wis[i]));
        Wtc[i] = __uint_as_float(tf32r(Wic[i]));
    } else {
        __shared__ float u[H], v[H];
        float su = 0.f, sv = 0.f;
#pragma unroll 8
        for (int k = 0; k < H; k++) {
            su += bos[k] * Ws2c[k * H + j];
            sv += boc[k] * Wc2s[k * H + j];
        }
        u[j] = su; v[j] = sv;
        __syncthreads();
        float t1 = 0.f, t2 = 0.f;
#pragma unroll 8
        for (int k = 0; k < H; k++) {
            t1 += u[k] * Wc2s[k * H + j];
            t2 += v[k] * Ws2c[k * H + j];
        }
        c[j]       = 0.34f * bos[j] + 0.165f * t1 + 0.495f * v[j];
        c[128 + j] = 0.34f * boc[j] + 0.165f * t2 + 0.495f * u[j];
    }
}

// ---------------- pre2: M quadrants ----------------
__global__ __launch_bounds__(128) void pre2_kernel(
    const float* __restrict__ Wos, const float* __restrict__ Woc,
    const float* __restrict__ Ws2c, const float* __restrict__ Wc2s,
    const float* __restrict__ H1, const float* __restrict__ H2,
    float* __restrict__ M)
{
    const int quad = blockIdx.x >> 7;
    const int r = blockIdx.x & 127;
    const int j = threadIdx.x;
    if (quad == 0) {
        float s = 0.f;
#pragma unroll 8
        for (int k = 0; k < H; k++) s += H1[r * H + k] * Wc2s[k * H + j];
        M[r * 256 + j] = 0.34f * Wos[r * H + j] + 0.165f * s;
    } else if (quad == 1) {
        M[r * 256 + 128 + j] = 0.495f * H1[r * H + j];
    } else if (quad == 2) {
        M[(128 + r) * 256 + j] = 0.495f * H2[r * H + j];
    } else {
        float s = 0.f;
#pragma unroll 8
        for (int k = 0; k < H; k++) s += H2[r * H + k] * Ws2c[k * H + j];
        M[(128 + r) * 256 + 128 + j] = 0.34f * Woc[r * H + j] + 0.165f * s;
    }
}

// ---------------- feat via tf32 MMA: A in smem (hi/lo), B via __ldg ----------------
struct FeatSmem {
    float2 A2[32][132];
    int2   xs[32];
};
#define FEAT_SMEM ((int)sizeof(FeatSmem))

__global__ __launch_bounds__(256) void feat_mma_kernel(
    const int* __restrict__ x,
    const float* __restrict__ e0s, const float* __restrict__ e1s,
    const float* __restrict__ Wts, const float* __restrict__ bs, float* __restrict__ outs,
    const float* __restrict__ e0c, const float* __restrict__ e1c,
    const float* __restrict__ Wtc, const float* __restrict__ bc, float* __restrict__ outc)
{
    extern __shared__ char smem_raw[];
    FeatSmem& S = *reinterpret_cast<FeatSmem*>(smem_raw);

    const int halfgrid = N_SRC / 32;
    const bool is_sim = blockIdx.x < halfgrid;
    const int  blk    = is_sim ? blockIdx.x : blockIdx.x - halfgrid;
    const float* emb0 = is_sim ? e0s : e0c;
    const float* emb1 = is_sim ? e1s : e1c;
    const float* Wt   = is_sim ? Wts : Wtc;
    const float* b    = is_sim ? bs  : bc;
    float*       out  = is_sim ? outs : outc;

    const int base = blk * 32;
    const int tid = threadIdx.x;

    if (tid < 32) S.xs[tid] = ((const int2*)x)[base + tid];
    __syncthreads();

    {
        const int k = tid & 127;
        const int rbase = (tid >> 7) * 16;
#pragma unroll
        for (int i = 0; i < 16; i++) {
            const int r = rbase + i;
            const float v = (k < 32) ? emb0[S.xs[r].x * 32 + k]
                                     : emb1[S.xs[r].y * 96 + (k - 32)];
            const uint32_t hb = tf32r(v);
            const float hf = __uint_as_float(hb);
            const uint32_t lb = tf32r(v - hf);
            S.A2[r][k] = make_float2(hf, __uint_as_float(lb));
        }
    }
    __syncthreads();

    const int lane = tid & 31, w = tid >> 5;
    const int mt = w & 1, nt = w >> 1;
    const int gid = lane >> 2, tig = lane & 3;
    const int rA0 = mt * 16 + gid;
    const int rA1 = rA0 + 8;

    float acc[4][4];
#pragma unroll
    for (int s = 0; s < 4; s++)
#pragma unroll
        for (int i = 0; i < 4; i++) acc[s][i] = 0.f;

#pragma unroll
    for (int kc = 0; kc < 16; kc++) {
        const int k0 = kc * 8;
        const float2 fa0 = S.A2[rA0][k0 + tig];
        const float2 fa1 = S.A2[rA1][k0 + tig];
        const float2 fa2 = S.A2[rA0][k0 + tig + 4];
        const float2 fa3 = S.A2[rA1][k0 + tig + 4];
        const uint32_t a0h = __float_as_uint(fa0.x), a0l = __float_as_uint(fa0.y);
        const uint32_t a1h = __float_as_uint(fa1.x), a1l = __float_as_uint(fa1.y);
        const uint32_t a2h = __float_as_uint(fa2.x), a2l = __float_as_uint(fa2.y);
        const uint32_t a3h = __float_as_uint(fa3.x), a3l = __float_as_uint(fa3.y);
#pragma unroll
        for (int sub = 0; sub < 4; sub++) {
            const int n = nt * 32 + sub * 8 + gid;
            const uint32_t b0 = __float_as_uint(__ldg(&Wt[(k0 + tig) * H + n]));
            const uint32_t b1 = __float_as_uint(__ldg(&Wt[(k0 + tig + 4) * H + n]));
            mma_tf32(acc[sub][0], acc[sub][1], acc[sub][2], acc[sub][3],
                     a0h, a1h, a2h, a3h, b0, b1);
            mma_tf32(acc[sub][0], acc[sub][1], acc[sub][2], acc[sub][3],
                     a0l, a1l, a2l, a3l, b0, b1);
        }
    }

#pragma unroll
    for (int sub = 0; sub < 4; sub++) {
        const int n = nt * 32 + sub * 8 + 2 * tig;
        const float2 bv = *(const float2*)&b[n];
        float2 r0 = make_float2(acc[sub][0] + bv.x, acc[sub][1] + bv.y);
        float2 r1 = make_float2(acc[sub][2] + bv.x, acc[sub][3] + bv.y);
        *(float2*)&out[(base + rA0) * H + n] = r0;
        *(float2*)&out[(base + rA1) * H + n] = r1;
    }
}

// ---------------- co-attention pool: fp16-packed tiles, fp16 MMA for L ----------------
// D/Q stored as packed half2 (word i = channels 2i, 2i+1), row stride 68 words
// -> banks = 4*gid + tig: conflict-free for MMA frags and channel reads.
// L via m16n8k16 f16 MMA (same 10-bit mantissa as tf32, half the bytes, k16/instr).
__global__ __launch_bounds__(256, 6) void attn_kernel(
    const float* __restrict__ feat_sim, const float* __restrict__ feat_cor,
    const int* __restrict__ neigh_sim, const int* __restrict__ neigh_cor,
    float* __restrict__ rst_sim, float* __restrict__ rst_cor)
{
    __shared__ uint32_t Dp[32][68];
    __shared__ uint32_t Qp[32][68];
    __shared__ float EsO[32 * 33];   // Es[m][k]; later reused as O[0..383]
    __shared__ float invcol[32];
    __shared__ float invrow[32];
    __shared__ float wv[32];
    __shared__ float vv[32];
    __shared__ float coef[32];
#define ES(m_, k_) EsO[(m_) * 33 + (k_)]

    const bool is_sim = blockIdx.x < N_DST;
    const int  node   = is_sim ? blockIdx.x : (blockIdx.x - N_DST);
    const float* feat = is_sim ? feat_sim : feat_cor;
    const int* idxD = is_sim ? neigh_cor : neigh_sim;   // sim: D = nf_cor
    const int* idxQ = is_sim ? neigh_sim : neigh_cor;
    float*     rst  = is_sim ? rst_sim : rst_cor;

    const int tid = threadIdx.x;
    const int lane = tid & 31;
    const int w = tid >> 5;

    // gather + fp16 pack: warp w loads rows [4w, 4w+4); lane covers 4 channels
#pragma unroll
    for (int i = 0; i < 4; i++) {
        const int r = w * 4 + i;
        const int id = idxD[node * 32 + r];
        const float4 dv = ((const float4*)feat)[id * 32 + lane];
        uint2 dw = make_uint2(packh2(dv.x, dv.y), packh2(dv.z, dv.w));
        *(uint2*)&Dp[r][2 * lane] = dw;
        const int iq = idxQ[node * 32 + r];
        const float4 qv = ((const float4*)feat)[iq * 32 + lane];
        uint2 qw = make_uint2(packh2(qv.x, qv.y), packh2(qv.z, qv.w));
        *(uint2*)&Qp[r][2 * lane] = qw;
    }
    __syncthreads();

    // ---- L via fp16 MMA (8 k16-chunks), then E = exp(L) ----
    {
        const int mt = w & 1;
        const int nt = w >> 1;
        const int gid = lane >> 2;
        const int tig = lane & 3;
        const int rA0 = mt * 16 + gid;
        const int rA1 = rA0 + 8;
        const int cn  = nt * 8 + gid;

        float c0 = 0.f, c1 = 0.f, c2 = 0.f, c3 = 0.f;
#pragma unroll
        for (int kc = 0; kc < 8; kc++) {
            const int k0 = kc * 8;
            const uint32_t a0 = Dp[rA0][k0 + tig];
            const uint32_t a1 = Dp[rA1][k0 + tig];
            const uint32_t a2 = Dp[rA0][k0 + tig + 4];
            const uint32_t a3 = Dp[rA1][k0 + tig + 4];
            const uint32_t b0 = Qp[cn][k0 + tig];
            const uint32_t b1 = Qp[cn][k0 + tig + 4];
            mma_f16(c0, c1, c2, c3, a0, a1, a2, a3, b0, b1);
        }
        const int ec = nt * 8 + 2 * tig;
        ES(rA0, ec)     = __expf(c0);
        ES(rA0, ec + 1) = __expf(c1);
        ES(rA1, ec)     = __expf(c2);
        ES(rA1, ec + 1) = __expf(c3);
    }
    __syncthreads();

    if (w == 0) {
        const int m = lane;
        float s = 0.f;
#pragma unroll
        for (int k = 0; k < 32; k++) s += ES(m, k);
        invrow[m] = __frcp_rn(s);
    } else if (w == 1) {
        const int k = lane;
        float s = 0.f;
#pragma unroll
        for (int m = 0; m < 32; m++) s += ES(m, k);
        invcol[k] = __frcp_rn(s);
    }
    __syncthreads();

    if (w == 0) {
        const int m = lane;
        float s = 0.f;
#pragma unroll
        for (int k = 0; k < 32; k++) s += ES(m, k) * invcol[k];
        wv[m] = s;
        coef[m] = s * invrow[m];
    }
    __syncthreads();

    if (w == 1) {
        const int k = lane;
        float s = 0.f;
#pragma unroll
        for (int m = 0; m < 32; m++) s += coef[m] * ES(m, k);
        vv[k] = s;
    }
    __syncthreads();
    // ---- EsO reused as O[0..383] ----
    float* O = EsO;

    // channel reductions on packed pairs: threads 0-63 Q (sq,scq), 64-127 D (sdw)
    if (tid < 64) {
        const int hw = tid;           // word = channels 2hw, 2hw+1
        float sq0 = 0.f, sq1 = 0.f, scq0 = 0.f, scq1 = 0.f;
#pragma unroll
        for (int m = 0; m < 32; m++) {
            const uint32_t qw = Qp[m][hw];
            const __half2 qh = *reinterpret_cast<const __half2*>(&qw);
            const float2 qf = __half22float2(qh);
            const float vm = vv[m];
            sq0  += qf.x;        sq1  += qf.y;
            scq0 += vm * qf.x;   scq1 += vm * qf.y;
        }
        O[2 * hw]         = sq0;  O[2 * hw + 1]         = sq1;
        O[2 * H + 2 * hw] = scq0; O[2 * H + 2 * hw + 1] = scq1;
    } else if (tid < 128) {
        const int hw = tid - 64;
        float sd0 = 0.f, sd1 = 0.f;
#pragma unroll
        for (int m = 0; m < 32; m++) {
            const uint32_t dw = Dp[m][hw];
            const __half2 dh = *reinterpret_cast<const __half2*>(&dw);
            const float2 df = __half22float2(dh);
            const float wm = wv[m];
            sd0 += wm * df.x;  sd1 += wm * df.y;
        }
        O[H + 2 * hw]     = sd0;  O[H + 2 * hw + 1]     = sd1;
    }
    __syncthreads();

    if (tid < 128) {
        const int h = tid;
        const float r = (O[3 * h] + O[3 * h + 1] + O[3 * h + 2]) * (1.f / 96.f);
        rst[node * H + h] = feat[node * H + h] + r;   // h_self exact from global
    }
#undef ES
}

// ---------------- fused final GEMM ----------------
__global__ __launch_bounds__(128) void mix_kernel(
    const float* __restrict__ rst_sim, const float* __restrict__ rst_cor,
    const float* __restrict__ M, const float* __restrict__ c,
    float* __restrict__ out)
{
    __shared__ float xb[256][34];
    const int base = blockIdx.x * 32;
    const int tid = threadIdx.x;

    for (int kk = tid; kk < 256; kk += 128) {
        const float* src = (kk < 128) ? (rst_sim + (size_t)base * H + kk)
                                      : (rst_cor + (size_t)base * H + (kk - 128));
#pragma unroll 4
        for (int r = 0; r < 32; r++) xb[kk][r] = src[r * H];
    }
    __syncthreads();

    const int j0 = tid;
    const int j1 = tid + 128;
    ULL acc0[16], acc1[16];
#pragma unroll
    for (int rp = 0; rp < 16; rp++) { acc0[rp] = 0ULL; acc1[rp] = 0ULL; }

#pragma unroll 2
    for (int k = 0; k < 256; k++) {
        const float w0 = M[k * 256 + j0];
        const float w1 = M[k * 256 + j1];
        const ULL wd0 = pk2(w0, w0);
        const ULL wd1 = pk2(w1, w1);
        const ULL* xp = (const ULL*)&xb[k][0];
#pragma unroll
        for (int rp = 0; rp < 16; rp++) {
            const ULL xv = xp[rp];
            ffma2(acc0[rp], xv, wd0);
            ffma2(acc1[rp], xv, wd1);
        }
    }

    const float c0 = c[j0], c1 = c[j1];
    float* o0 = out + j0;
    float* o1 = out + (size_t)N_DST * H + tid;
#pragma unroll
    for (int rp = 0; rp < 16; rp++) {
        const float2 f0 = upk2(acc0[rp]);
        const float2 f1 = upk2(acc1[rp]);
        o0[(size_t)(base + 2 * rp + 0) * H] = f0.x + c0;
        o0[(size_t)(base + 2 * rp + 1) * H] = f0.y + c0;
        o1[(size_t)(base + 2 * rp + 0) * H] = f1.x + c1;
        o1[(size_t)(base + 2 * rp + 1) * H] = f1.y + c1;
    }
}

// ---------------- launch ----------------
extern "C" void kernel_launch(void* const* d_in, const int* in_sizes, int n_in,
                              void* d_out, int out_size)
{
    const int*   x         = (const int*)d_in[0];
    const int*   neigh_sim = (const int*)d_in[1];
    const int*   neigh_cor = (const int*)d_in[2];
    const float* emb0_sim  = (const float*)d_in[3];
    const float* emb1_sim  = (const float*)d_in[4];
    const float* emb0_cor  = (const float*)d_in[5];
    const float* emb1_cor  = (const float*)d_in[6];
    const float* W_in_sim  = (const float*)d_in[7];
    const float* b_in_sim  = (const float*)d_in[8];
    const float* W_in_cor  = (const float*)d_in[9];
    const float* b_in_cor  = (const float*)d_in[10];
    const float* W_out_sim = (const float*)d_in[11];
    const float* b_out_sim = (const float*)d_in[12];
    const float* W_out_cor = (const float*)d_in[13];
    const float* b_out_cor = (const float*)d_in[14];
    const float* W_sim2cor = (const float*)d_in[15];
    const float* W_cor2sim = (const float*)d_in[16];

    float *feat_sim, *feat_cor, *rst_sim, *rst_cor, *Wts, *Wtc, *H1, *H2, *M, *c;
    cudaGetSymbolAddress((void**)&feat_sim, g_feat_sim);
    cudaGetSymbolAddress((void**)&feat_cor, g_feat_cor);
    cudaGetSymbolAddress((void**)&rst_sim,  g_rst_sim);
    cudaGetSymbolAddress((void**)&rst_cor,  g_rst_cor);
    cudaGetSymbolAddress((void**)&Wts,      g_Wts);
    cudaGetSymbolAddress((void**)&Wtc,      g_Wtc);
    cudaGetSymbolAddress((void**)&H1,       g_H1);
    cudaGetSymbolAddress((void**)&H2,       g_H2);
    cudaGetSymbolAddress((void**)&M,        g_M);
    cudaGetSymbolAddress((void**)&c,        g_c);

    float* out = (float*)d_out;

    cudaFuncSetAttribute(feat_mma_kernel, cudaFuncAttributeMaxDynamicSharedMemorySize, FEAT_SMEM);

    preA_kernel<<<385, 128>>>(W_out_sim, W_sim2cor, W_out_cor, W_cor2sim,
                              W_in_sim, W_in_cor, b_out_sim, b_out_cor,
                              H1, H2, Wts, Wtc, c);
    pre2_kernel<<<4 * H, 128>>>(W_out_sim, W_out_cor, W_sim2cor, W_cor2sim, H1, H2, M);

    feat_mma_kernel<<<2 * (N_SRC / 32), 256, FEAT_SMEM>>>(x,
        emb0_sim, emb1_sim, Wts, b_in_sim, feat_sim,
        emb0_cor, emb1_cor, Wtc, b_in_cor, feat_cor);

    attn_kernel<<<2 * N_DST, 256>>>(feat_sim, feat_cor, neigh_sim, neigh_cor,
                                    rst_sim, rst_cor);

    mix_kernel<<<N_DST / 32, 128>>>(rst_sim, rst_cor, M, c, out);
}